// round 6
// baseline (speedup 1.0000x reference)
#include <cuda_runtime.h>
#include <cuda_bf16.h>
#include <cstdint>
#include <math.h>

// ---------------------------------------------------------------------------
// Problem constants
// ---------------------------------------------------------------------------
#define SQ   128            // seq len
#define BB   128            // batch
#define EE   256            // embed dim
#define HH   256            // hidden
#define G4   1024           // 4*H
#define D2   512            // 2*H
#define MBS  (BB*SQ)        // 16384
#define MX   (3*MBS)        // 49152 rows of X
#define OUTREG (BB*SQ*D2)   // 8388608 floats per output tensor

// LSTM-mma geometry
#define WPAD 260
#define HPAD 260
#define GPAD 132
// W[128][WPAD] + h[64][HPAD] + Ghalf[32][GPAD]  (all 4B)
#define LSTM_SMEM_BYTES ((128*WPAD + 64*HPAD + 32*GPAD) * 4)   // 216,576 B

// ---------------------------------------------------------------------------
// Device scratch
// ---------------------------------------------------------------------------
__device__ float g_X    [3*MBS*EE];     //  50 MB  embedded inputs
__device__ float g_XpreF[3*MBS*G4];     // 201 MB  X@Wih_f^T + bias_f
__device__ float g_XpreB[3*MBS*G4];     // 201 MB
__device__ float g_biasf[G4];
__device__ float g_biasb[G4];
__device__ float g_Y    [3*MBS*D2];     // 100 MB  BiLSTM outputs [seq][b][s][2H]
__device__ float g_Ct   [2*MBS*D2];     //  67 MB  tanh(S1(C))
__device__ float g_YqT  [MBS*D2];       //  33 MB  per-batch transpose of Q stream
__device__ float g_MQT  [MBS*D2];       //  33 MB  per-batch transpose of MQ
__device__ float g_Hm   [BB*SQ*SQ];     // 8.4 MB
__device__ float g_AQ   [BB*SQ*SQ];
__device__ float g_AC   [BB*SQ*SQ];

// ---------------------------------------------------------------------------
// tf32 helpers
// ---------------------------------------------------------------------------
__device__ __forceinline__ unsigned f2tf(float f) {
    unsigned r;
    asm("cvt.rna.tf32.f32 %0, %1;" : "=r"(r) : "f"(f));
    return r;
}
__device__ __forceinline__ void mma_tf32(float* d, const unsigned a[4],
                                         unsigned b0, unsigned b1) {
    asm volatile(
        "mma.sync.aligned.m16n8k8.row.col.f32.tf32.tf32.f32 "
        "{%0,%1,%2,%3},{%4,%5,%6,%7},{%8,%9},{%0,%1,%2,%3};"
        : "+f"(d[0]), "+f"(d[1]), "+f"(d[2]), "+f"(d[3])
        : "r"(a[0]), "r"(a[1]), "r"(a[2]), "r"(a[3]), "r"(b0), "r"(b1));
}
__device__ __forceinline__ unsigned smem_u32(const void* p) {
    unsigned a;
    asm("{ .reg .u64 t; cvta.to.shared.u64 t, %1; cvt.u32.u64 %0, t; }"
        : "=r"(a) : "l"(p));
    return a;
}

// ---------------------------------------------------------------------------
// Prep: bias = bih + bhh
// ---------------------------------------------------------------------------
__global__ void prep_kernel(const float* __restrict__ bihF, const float* __restrict__ bhhF,
                            const float* __restrict__ bihB, const float* __restrict__ bhhB,
                            float* __restrict__ biasf, float* __restrict__ biasb)
{
    int gid = blockIdx.x * 256 + threadIdx.x;
    if (gid < G4) {
        biasf[gid] = bihF[gid] + bhhF[gid];
        biasb[gid] = bihB[gid] + bhhB[gid];
    }
}

// ---------------------------------------------------------------------------
// Embedding gather
// ---------------------------------------------------------------------------
__global__ void embed_kernel(const int* __restrict__ tq, const int* __restrict__ tc,
                             const int* __restrict__ tc2,
                             const float4* __restrict__ emb, float4* __restrict__ X)
{
    int gid = blockIdx.x * 256 + threadIdx.x;      // 3145728 total
    int c4  = gid & 63;
    int row = gid >> 6;
    int seq = row / MBS;
    int rb  = row - seq * MBS;
    int b   = rb >> 7, s = rb & 127;
    const int* tok = (seq == 0) ? tq : ((seq == 1) ? tc : tc2);
    int t = tok[s * BB + b];
    X[(size_t)row * 64 + c4] = emb[(size_t)t * 64 + c4];
}

// ---------------------------------------------------------------------------
// tf32 tensor-core GEMM, NT form (verified R4)
// ---------------------------------------------------------------------------
template<int EPI>   // 0=none, 1=+bias[n], 2=tanh(x+bias[n])
__global__ __launch_bounds__(256) void tgemm_kernel(
    int M, int N, int K,
    const float* __restrict__ A, int lda, size_t sA,
    const float* __restrict__ B, int ldb, size_t sB,
    float* __restrict__ C, int ldc, size_t sC,
    const float* __restrict__ bias)
{
    __shared__ unsigned As[128 * 36];
    __shared__ unsigned Bs[128 * 36];
    int bx = blockIdx.x, by = blockIdx.y, bz = blockIdx.z;
    const float* Ap = A + (size_t)bz * sA + (size_t)by * 128 * lda;
    const float* Bp = B + (size_t)bz * sB + (size_t)bx * 128 * ldb;
    float* Cp = C + (size_t)bz * sC + (size_t)by * 128 * ldc + (size_t)bx * 128;

    int tid = threadIdx.x, lane = tid & 31, warp = tid >> 5;
    int wm = warp & 3, wn = warp >> 2;
    int ly = lane >> 2, lx = lane & 3;

    float acc[2][8][4];
#pragma unroll
    for (int im = 0; im < 2; im++)
#pragma unroll
        for (int nt = 0; nt < 8; nt++)
#pragma unroll
            for (int j = 0; j < 4; j++) acc[im][nt][j] = 0.f;

    for (int k0 = 0; k0 < K; k0 += 32) {
#pragma unroll
        for (int i = 0; i < 4; i++) {
            int fid = tid + 256 * i;
            int row = fid >> 3, c4 = (fid & 7) * 4;
            float4 av = *reinterpret_cast<const float4*>(Ap + (size_t)row * lda + k0 + c4);
            uint4 aw; aw.x = f2tf(av.x); aw.y = f2tf(av.y); aw.z = f2tf(av.z); aw.w = f2tf(av.w);
            *reinterpret_cast<uint4*>(&As[row * 36 + c4]) = aw;
            float4 bv = *reinterpret_cast<const float4*>(Bp + (size_t)row * ldb + k0 + c4);
            uint4 bw; bw.x = f2tf(bv.x); bw.y = f2tf(bv.y); bw.z = f2tf(bv.z); bw.w = f2tf(bv.w);
            *reinterpret_cast<uint4*>(&Bs[row * 36 + c4]) = bw;
        }
        __syncthreads();
#pragma unroll
        for (int kk = 0; kk < 4; kk++) {
            int k8 = kk * 8;
            unsigned a[2][4];
#pragma unroll
            for (int im = 0; im < 2; im++) {
                int rb = wm * 32 + im * 16;
                a[im][0] = As[(rb + ly) * 36 + k8 + lx];
                a[im][1] = As[(rb + ly + 8) * 36 + k8 + lx];
                a[im][2] = As[(rb + ly) * 36 + k8 + lx + 4];
                a[im][3] = As[(rb + ly + 8) * 36 + k8 + lx + 4];
            }
#pragma unroll
            for (int nt = 0; nt < 8; nt++) {
                int n = wn * 64 + nt * 8 + ly;
                unsigned b0 = Bs[n * 36 + k8 + lx];
                unsigned b1 = Bs[n * 36 + k8 + lx + 4];
                mma_tf32(acc[0][nt], a[0], b0, b1);
                mma_tf32(acc[1][nt], a[1], b0, b1);
            }
        }
        __syncthreads();
    }

#pragma unroll
    for (int im = 0; im < 2; im++) {
#pragma unroll
        for (int nt = 0; nt < 8; nt++) {
            int n0 = wn * 64 + nt * 8 + lx * 2;
            int r0 = wm * 32 + im * 16 + ly;
            float2 v0 = make_float2(acc[im][nt][0], acc[im][nt][1]);
            float2 v1 = make_float2(acc[im][nt][2], acc[im][nt][3]);
            if constexpr (EPI >= 1) {
                float b0v = bias[bx * 128 + n0], b1v = bias[bx * 128 + n0 + 1];
                v0.x += b0v; v0.y += b1v; v1.x += b0v; v1.y += b1v;
            }
            if constexpr (EPI == 2) {
                v0.x = tanhf(v0.x); v0.y = tanhf(v0.y);
                v1.x = tanhf(v1.x); v1.y = tanhf(v1.y);
            }
            *reinterpret_cast<float2*>(&Cp[(size_t)r0 * ldc + n0]) = v0;
            *reinterpret_cast<float2*>(&Cp[(size_t)(r0 + 8) * ldc + n0]) = v1;
        }
    }
}

// ---------------------------------------------------------------------------
// Batched transpose
// ---------------------------------------------------------------------------
__global__ void transpose_kernel(const float* __restrict__ in, float* __restrict__ out)
{
    __shared__ float tile[32][33];
    int b = blockIdx.z;
    const float* ip = in + (size_t)b * SQ * D2;
    float* op = out + (size_t)b * SQ * D2;
    int c0 = blockIdx.x * 32, r0 = blockIdx.y * 32;
    int x = threadIdx.x, y = threadIdx.y;
#pragma unroll
    for (int j = 0; j < 32; j += 8)
        tile[y + j][x] = ip[(size_t)(r0 + y + j) * D2 + c0 + x];
    __syncthreads();
#pragma unroll
    for (int j = 0; j < 32; j += 8)
        op[(size_t)(c0 + y + j) * SQ + r0 + x] = tile[x][y + j];
}

// ---------------------------------------------------------------------------
// LSTM recurrence, tensor-core + 8-CTA-cluster DSMEM exchange.
// Grid 96 = 12 clusters x 8 ranks; rank gg = gate-group; cluster = (stream, half).
// Per step:
//   MMA (reads smH) -> sync -> cluster arrive#1
//   G staging + epilogue in two half passes (separate smG, local work)
//   cluster wait#1 -> scatter h (tf32) to all 8 ranks' smH -> arrive+wait#2
// ---------------------------------------------------------------------------
__global__ __launch_bounds__(256) __cluster_dims__(8, 1, 1)
void lstm_mma_kernel(
    const float* __restrict__ xpreF, const float* __restrict__ xpreB,
    const float* __restrict__ WhhF, const float* __restrict__ WhhB,
    const float* __restrict__ h_q, const float* __restrict__ c_q,
    const float* __restrict__ h_c, const float* __restrict__ c_c,
    const float* __restrict__ h_c2, const float* __restrict__ c_c2,
    float* __restrict__ Y)
{
    extern __shared__ unsigned sm[];
    unsigned* smW = sm;                              // [128][WPAD]
    unsigned* smH = sm + 128 * WPAD;                 // [64][HPAD]
    float*    smG = (float*)(sm + 128 * WPAD + 64 * HPAD);   // [32][GPAD]

    int bx  = blockIdx.x;
    int sd  = bx >> 4;                   // 0..5  (seq,dir)
    int bg  = (bx >> 3) & 1;             // batch half
    int gg  = bx & 7;                    // gate group == cluster rank
    int seq = sd >> 1, dir = sd & 1;

    int tid  = threadIdx.x;
    int lane = tid & 31, warp = tid >> 5;
    int ly = lane >> 2, lx = lane & 3;
    int mt = warp & 3;                   // m-tile (16 rows)
    int nh = warp >> 2;                  // n-half (64 gate-cols)

    const float* xpre = (dir ? xpreB : xpreF) + (size_t)seq * MBS * G4;
    const float* Whh  = dir ? WhhB : WhhF;
    const float* h0p  = (seq == 0) ? h_q : ((seq == 1) ? h_c : h_c2);
    const float* c0p  = (seq == 0) ? c_q : ((seq == 1) ? c_c : c_c2);

    // ---- weights into smem (tf32), rows = g*32+u within this gate group ----
    for (int i = tid; i < 128 * 256; i += 256) {
        int r = i >> 8, c = i & 255;
        int g = r >> 5, u_ = r & 31;
        smW[r * WPAD + c] = f2tf(Whh[(size_t)(g * 256 + gg * 32 + u_) * 256 + c]);
    }
    // ---- initial h (full 64x256) into smem (tf32) ----
    for (int i = tid; i < 64 * 64; i += 256) {
        int r = i >> 6, c4 = (i & 63) * 4;
        float4 v = *(const float4*)&h0p[((size_t)(dir * BB + bg * 64 + r)) * HH + c4];
        uint4 w; w.x = f2tf(v.x); w.y = f2tf(v.y); w.z = f2tf(v.z); w.w = f2tf(v.w);
        *(uint4*)&smH[r * HPAD + c4] = w;
    }
    // ---- c state: thread owns unit u, rows mb..mb+7 ----
    int u  = tid & 31;
    int mb = warp * 8;
    float cst[8];
#pragma unroll
    for (int p = 0; p < 8; p++)
        cst[p] = c0p[((size_t)(dir * BB + bg * 64 + mb + p)) * HH + gg * 32 + u];
    __syncthreads();

    // ---- per-rank remote smH base addresses ----
    unsigned smH_b = smem_u32(smH);
    unsigned dstBase[8];
#pragma unroll
    for (int r = 0; r < 8; r++)
        asm("mapa.shared::cluster.u32 %0, %1, %2;"
            : "=r"(dstBase[r]) : "r"(smH_b), "r"(r));

    float hv[8];

    for (int t = 0; t < SQ; t++) {
        int te = dir ? (SQ - 1 - t) : t;

        // ---- MMA phase (reads smH) ----
        float acc[8][4];
#pragma unroll
        for (int n = 0; n < 8; n++)
#pragma unroll
            for (int j = 0; j < 4; j++) acc[n][j] = 0.f;

        const unsigned* hA = smH + (mt * 16 + ly) * HPAD + lx;
#pragma unroll 4
        for (int k0 = 0; k0 < 256; k0 += 8) {
            unsigned a[4];
            a[0] = hA[k0];
            a[1] = hA[k0 + 8 * HPAD];
            a[2] = hA[k0 + 4];
            a[3] = hA[k0 + 8 * HPAD + 4];
#pragma unroll
            for (int nt = 0; nt < 8; nt++) {
                const unsigned* wB = smW + (nh * 64 + nt * 8 + ly) * WPAD + k0 + lx;
                mma_tf32(acc[nt], a, wB[0], wB[4]);
            }
        }
        __syncthreads();                                   // all smH reads done
        asm volatile("barrier.cluster.arrive.aligned;" ::: "memory");   // #1 arrive

        // ---- pass A: rows 0..31 ----
        if (mt < 2) {
#pragma unroll
            for (int nt = 0; nt < 8; nt++) {
                int n0 = nh * 64 + nt * 8 + lx * 2;
                int r0 = mt * 16 + ly;
                *(float2*)&smG[r0 * GPAD + n0]       = make_float2(acc[nt][0], acc[nt][1]);
                *(float2*)&smG[(r0 + 8) * GPAD + n0] = make_float2(acc[nt][2], acc[nt][3]);
            }
        }
        __syncthreads();
        if (warp < 4) {
#pragma unroll
            for (int p = 0; p < 8; p++) {
                int m = mb + p;      // 0..31
                const float* xp = &xpre[(((size_t)(bg * 64 + m)) * SQ + te) * G4 + gg * 32 + u];
                float gi = smG[m * GPAD +      u] + xp[0];
                float gf = smG[m * GPAD + 32 + u] + xp[256];
                float gc = smG[m * GPAD + 64 + u] + xp[512];
                float go = smG[m * GPAD + 96 + u] + xp[768];
                float i_ = 1.f / (1.f + __expf(-gi));
                float f_ = 1.f / (1.f + __expf(-gf));
                float g_ = tanhf(gc);
                float o_ = 1.f / (1.f + __expf(-go));
                float c  = f_ * cst[p] + i_ * g_;
                cst[p] = c;
                float h = o_ * tanhf(c);
                hv[p] = h;
                Y[(((size_t)(seq * BB + bg * 64 + m)) * SQ + te) * D2 + dir * HH + gg * 32 + u] = h;
            }
        }
        __syncthreads();
        // ---- pass B: rows 32..63 ----
        if (mt >= 2) {
#pragma unroll
            for (int nt = 0; nt < 8; nt++) {
                int n0 = nh * 64 + nt * 8 + lx * 2;
                int r0 = (mt - 2) * 16 + ly;
                *(float2*)&smG[r0 * GPAD + n0]       = make_float2(acc[nt][0], acc[nt][1]);
                *(float2*)&smG[(r0 + 8) * GPAD + n0] = make_float2(acc[nt][2], acc[nt][3]);
            }
        }
        __syncthreads();
        if (warp >= 4) {
#pragma unroll
            for (int p = 0; p < 8; p++) {
                int m = mb + p;      // 32..63
                const float* xp = &xpre[(((size_t)(bg * 64 + m)) * SQ + te) * G4 + gg * 32 + u];
                float gi = smG[(m - 32) * GPAD +      u] + xp[0];
                float gf = smG[(m - 32) * GPAD + 32 + u] + xp[256];
                float gc = smG[(m - 32) * GPAD + 64 + u] + xp[512];
                float go = smG[(m - 32) * GPAD + 96 + u] + xp[768];
                float i_ = 1.f / (1.f + __expf(-gi));
                float f_ = 1.f / (1.f + __expf(-gf));
                float g_ = tanhf(gc);
                float o_ = 1.f / (1.f + __expf(-go));
                float c  = f_ * cst[p] + i_ * g_;
                cst[p] = c;
                float h = o_ * tanhf(c);
                hv[p] = h;
                Y[(((size_t)(seq * BB + bg * 64 + m)) * SQ + te) * D2 + dir * HH + gg * 32 + u] = h;
            }
        }

        // ---- wait: all cluster CTAs done reading old h ----
        asm volatile("barrier.cluster.wait.aligned;" ::: "memory");     // #1 wait

        // ---- scatter new h (tf32) to all 8 ranks' smH (incl. self) ----
#pragma unroll
        for (int p = 0; p < 8; p++) {
            unsigned tv = f2tf(hv[p]);
            unsigned off = ((unsigned)(mb + p) * HPAD + gg * 32 + u) * 4;
#pragma unroll
            for (int r = 0; r < 8; r++)
                asm volatile("st.shared::cluster.u32 [%0], %1;"
                             :: "r"(dstBase[r] + off), "r"(tv) : "memory");
        }

        // ---- barrier #2: stores visible everywhere ----
        asm volatile("barrier.cluster.arrive.aligned;" ::: "memory");
        asm volatile("barrier.cluster.wait.aligned;" ::: "memory");
    }
}

// ---------------------------------------------------------------------------
// Softmax kernels
// ---------------------------------------------------------------------------
__global__ void row_softmax(const float* __restrict__ Hm, float* __restrict__ AQ)
{
    int warp = (blockIdx.x * blockDim.x + threadIdx.x) >> 5;
    int lane = threadIdx.x & 31;
    const float* base = Hm + (size_t)warp * SQ;
    float v[4], m = -1e30f;
#pragma unroll
    for (int u = 0; u < 4; u++) { v[u] = base[lane + 32 * u]; m = fmaxf(m, v[u]); }
#pragma unroll
    for (int o = 16; o > 0; o >>= 1) m = fmaxf(m, __shfl_xor_sync(0xffffffffu, m, o));
    float s = 0.f;
#pragma unroll
    for (int u = 0; u < 4; u++) { v[u] = __expf(v[u] - m); s += v[u]; }
#pragma unroll
    for (int o = 16; o > 0; o >>= 1) s += __shfl_xor_sync(0xffffffffu, s, o);
    float inv = 1.f / s;
    float* out = AQ + (size_t)warp * SQ;
#pragma unroll
    for (int u = 0; u < 4; u++) out[lane + 32 * u] = v[u] * inv;
}

__global__ void col_softmax(const float* __restrict__ Hm, float* __restrict__ AC)
{
    int warp = (blockIdx.x * blockDim.x + threadIdx.x) >> 5;
    int lane = threadIdx.x & 31;
    int b = warp >> 7, s = warp & 127;
    const float* base = Hm + (size_t)b * SQ * SQ + s;
    float v[4], m = -1e30f;
#pragma unroll
    for (int u = 0; u < 4; u++) { v[u] = base[(size_t)(lane + 32 * u) * SQ]; m = fmaxf(m, v[u]); }
#pragma unroll
    for (int o = 16; o > 0; o >>= 1) m = fmaxf(m, __shfl_xor_sync(0xffffffffu, m, o));
    float sm = 0.f;
#pragma unroll
    for (int u = 0; u < 4; u++) { v[u] = __expf(v[u] - m); sm += v[u]; }
#pragma unroll
    for (int o = 16; o > 0; o >>= 1) sm += __shfl_xor_sync(0xffffffffu, sm, o);
    float inv = 1.f / sm;
    float* out = AC + (size_t)b * SQ * SQ + (size_t)s * SQ;
#pragma unroll
    for (int u = 0; u < 4; u++) out[lane + 32 * u] = v[u] * inv;
}

// ---------------------------------------------------------------------------
// Host-side GEMM dispatch
// ---------------------------------------------------------------------------
static void run_tgemm(int epi, int M, int N, int K,
                      const float* A, int lda, size_t sA,
                      const float* B, int ldb, size_t sB,
                      float* C, int ldc, size_t sC,
                      const float* bias, int batch)
{
    dim3 grid(N / 128, M / 128, batch), block(256);
    if (epi == 0)      tgemm_kernel<0><<<grid, block>>>(M, N, K, A, lda, sA, B, ldb, sB, C, ldc, sC, bias);
    else if (epi == 1) tgemm_kernel<1><<<grid, block>>>(M, N, K, A, lda, sA, B, ldb, sB, C, ldc, sC, bias);
    else               tgemm_kernel<2><<<grid, block>>>(M, N, K, A, lda, sA, B, ldb, sB, C, ldc, sC, bias);
}

// ---------------------------------------------------------------------------
// kernel_launch
// ---------------------------------------------------------------------------
extern "C" void kernel_launch(void* const* d_in, const int* in_sizes, int n_in,
                              void* d_out, int out_size)
{
    (void)in_sizes; (void)n_in; (void)out_size;
    const int*   inQ   = (const int*)d_in[1];
    const int*   inC   = (const int*)d_in[2];
    const int*   inC2  = (const int*)d_in[3];
    const float* hidQ  = (const float*)d_in[4];
    const float* celQ  = (const float*)d_in[5];
    const float* hidC  = (const float*)d_in[6];
    const float* celC  = (const float*)d_in[7];
    const float* hidC2 = (const float*)d_in[8];
    const float* celC2 = (const float*)d_in[9];
    const float* emb   = (const float*)d_in[10];
    const float* WihF  = (const float*)d_in[11];
    const float* WhhF  = (const float*)d_in[12];
    const float* bihF  = (const float*)d_in[13];
    const float* bhhF  = (const float*)d_in[14];
    const float* WihB  = (const float*)d_in[15];
    const float* WhhB  = (const float*)d_in[16];
    const float* bihB  = (const float*)d_in[17];
    const float* bhhB  = (const float*)d_in[18];
    const float* S1W   = (const float*)d_in[19];
    const float* S1b   = (const float*)d_in[20];
    float* out = (float*)d_out;

    void *pX, *pXpF, *pXpB, *pBf, *pBb, *pY, *pCt, *pYqT, *pMQT, *pHm, *pAQ, *pAC;
    cudaGetSymbolAddress(&pX,   g_X);
    cudaGetSymbolAddress(&pXpF, g_XpreF);
    cudaGetSymbolAddress(&pXpB, g_XpreB);
    cudaGetSymbolAddress(&pBf,  g_biasf);
    cudaGetSymbolAddress(&pBb,  g_biasb);
    cudaGetSymbolAddress(&pY,   g_Y);
    cudaGetSymbolAddress(&pCt,  g_Ct);
    cudaGetSymbolAddress(&pYqT, g_YqT);
    cudaGetSymbolAddress(&pMQT, g_MQT);
    cudaGetSymbolAddress(&pHm,  g_Hm);
    cudaGetSymbolAddress(&pAQ,  g_AQ);
    cudaGetSymbolAddress(&pAC,  g_AC);
    float* X    = (float*)pX;
    float* XpF  = (float*)pXpF;
    float* XpB  = (float*)pXpB;
    float* Bf   = (float*)pBf;
    float* Bb   = (float*)pBb;
    float* Y    = (float*)pY;
    float* Ct   = (float*)pCt;
    float* YqT  = (float*)pYqT;
    float* MQT  = (float*)pMQT;
    float* Hm   = (float*)pHm;
    float* AQ   = (float*)pAQ;
    float* AC   = (float*)pAC;

    cudaFuncSetAttribute(lstm_mma_kernel,
                         cudaFuncAttributeMaxDynamicSharedMemorySize,
                         LSTM_SMEM_BYTES);

    // 1. prep: bias fold
    prep_kernel<<<4, 256>>>(bihF, bhhF, bihB, bhhB, Bf, Bb);

    // 2. embedding gather
    embed_kernel<<<12288, 256>>>(inQ, inC, inC2, (const float4*)emb, (float4*)X);

    // 3. input GEMMs: Xpre = X @ Wih^T + (bih+bhh)
    run_tgemm(1, MX, G4, EE, X, EE, 0, WihF, EE, 0, XpF, G4, 0, Bf, 1);
    run_tgemm(1, MX, G4, EE, X, EE, 0, WihB, EE, 0, XpB, G4, 0, Bb, 1);

    // 4. recurrence (tensor-core, 12 clusters x 8 CTAs, DSMEM exchange)
    lstm_mma_kernel<<<96, 256, LSTM_SMEM_BYTES>>>(
        XpF, XpB, WhhF, WhhB,
        hidQ, celQ, hidC, celC, hidC2, celC2, Y);

    // 5. Ct = tanh(Y_c @ S1_W^T + S1_b)
    run_tgemm(2, MBS, D2, D2, Y + (size_t)1 * MBS * D2, D2, 0,
              S1W, D2, 0, Ct, D2, 0, S1b, 1);
    run_tgemm(2, MBS, D2, D2, Y + (size_t)2 * MBS * D2, D2, 0,
              S1W, D2, 0, Ct + (size_t)MBS * D2, D2, 0, S1b, 1);

    // 5b. Yq^T for the MQ GEMM's B operand
    {
        dim3 tg(D2 / 32, SQ / 32, BB), tb(32, 8);
        transpose_kernel<<<tg, tb>>>(Y, YqT);
    }

    // 6. attention for pairs (Q,C) and (Q,C2)
    for (int p = 0; p < 2; p++) {
        run_tgemm(0, SQ, SQ, D2,
                  Y, D2, (size_t)SQ * D2,
                  Ct + (size_t)p * MBS * D2, D2, (size_t)SQ * D2,
                  Hm, SQ, (size_t)SQ * SQ, nullptr, BB);
        row_softmax<<<2048, 256>>>(Hm, AQ);
        col_softmax<<<2048, 256>>>(Hm, AC);
        float* outMQ = out + (size_t)(2 * p) * OUTREG;
        float* outMC = out + (size_t)(2 * p + 1) * OUTREG;
        run_tgemm(0, SQ, D2, SQ,
                  AQ, SQ, (size_t)SQ * SQ,
                  YqT, SQ, (size_t)SQ * D2,
                  outMQ, D2, (size_t)SQ * D2, nullptr, BB);
        {
            dim3 tg(D2 / 32, SQ / 32, BB), tb(32, 8);
            transpose_kernel<<<tg, tb>>>(outMQ, MQT);
        }
        run_tgemm(0, SQ, D2, SQ,
                  AC, SQ, (size_t)SQ * SQ,
                  MQT, SQ, (size_t)SQ * D2,
                  outMC, D2, (size_t)SQ * D2, nullptr, BB);
    }
}

// round 9
// speedup vs baseline: 1.3988x; 1.3988x over previous
#include <cuda_runtime.h>
#include <cuda_bf16.h>
#include <cstdint>
#include <math.h>

// ---------------------------------------------------------------------------
// Problem constants
// ---------------------------------------------------------------------------
#define SQ   128            // seq len
#define BB   128            // batch
#define EE   256            // embed dim
#define HH   256            // hidden
#define G4   1024           // 4*H
#define D2   512            // 2*H
#define MBS  (BB*SQ)        // 16384
#define MX   (3*MBS)        // 49152 rows of X
#define OUTREG (BB*SQ*D2)   // 8388608 floats per output tensor

// LSTM-mma geometry (R4 verified)
#define WPAD 260
#define HPAD 260
#define GPAD 132
#define LSTM_SMEM_BYTES ((128*WPAD + 64*HPAD) * 4)   // 199,680 B

// tgemm dynamic smem: 2 buffers x (A + B) x 128*36 words
#define TG_BUF (128 * 36)
#define TGEMM_SMEM_BYTES (4 * TG_BUF * 4)            // 73,728 B

// ---------------------------------------------------------------------------
// Device scratch
// ---------------------------------------------------------------------------
__device__ float g_X    [3*MBS*EE];     //  50 MB  embedded inputs (tf32-rounded)
__device__ float g_XpreF[3*MBS*G4];     // 201 MB  X@Wih_f^T + bias_f  (fp32)
__device__ float g_XpreB[3*MBS*G4];     // 201 MB
__device__ float g_WihFr[G4*EE];        //   1 MB  tf32-rounded Wih_f
__device__ float g_WihBr[G4*EE];        //   1 MB  tf32-rounded Wih_b
__device__ float g_S1Wr [D2*D2];        //   1 MB  tf32-rounded S1_W
__device__ float g_biasf[G4];
__device__ float g_biasb[G4];
__device__ float g_Y    [3*MBS*D2];     // 100 MB  BiLSTM outputs (tf32-rounded)
__device__ float g_Ct   [2*MBS*D2];     //  67 MB  tanh(S1(C)) (tf32-rounded)
__device__ float g_YqT  [MBS*D2];       //  33 MB  transpose of Q stream (rounded)
__device__ float g_MQT  [MBS*D2];       //  33 MB  transpose of MQ (rounded)
__device__ float g_Hm   [BB*SQ*SQ];     // 8.4 MB  logits (fp32)
__device__ float g_AQ   [BB*SQ*SQ];     //          softmax (tf32-rounded)
__device__ float g_AC   [BB*SQ*SQ];
__device__ int   g_bar  [12];           // barrier counters (6 streams x 2 halves)

// ---------------------------------------------------------------------------
// tf32 helpers
// ---------------------------------------------------------------------------
__device__ __forceinline__ unsigned f2tf(float f) {
    unsigned r;
    asm("cvt.rna.tf32.f32 %0, %1;" : "=r"(r) : "f"(f));
    return r;
}
__device__ __forceinline__ float rndtf(float f) {     // rna tf32 round, kept in fp32
    return __uint_as_float(f2tf(f));
}
__device__ __forceinline__ void mma_tf32(float* d, const unsigned a[4],
                                         unsigned b0, unsigned b1) {
    asm volatile(
        "mma.sync.aligned.m16n8k8.row.col.f32.tf32.tf32.f32 "
        "{%0,%1,%2,%3},{%4,%5,%6,%7},{%8,%9},{%0,%1,%2,%3};"
        : "+f"(d[0]), "+f"(d[1]), "+f"(d[2]), "+f"(d[3])
        : "r"(a[0]), "r"(a[1]), "r"(a[2]), "r"(a[3]), "r"(b0), "r"(b1));
}
__device__ __forceinline__ unsigned smem_u32(const void* p) {
    unsigned a;
    asm("{ .reg .u64 t; cvta.to.shared.u64 t, %1; cvt.u32.u64 %0, t; }"
        : "=r"(a) : "l"(p));
    return a;
}

// ---------------------------------------------------------------------------
// Prep: bias fold, barrier reset, tf32-rounded weight copies.
// Grid: 1024 x 256 = 262144 threads (covers 1024x256 Wih and 512x512 S1W).
// ---------------------------------------------------------------------------
__global__ void prep_kernel(const float* __restrict__ bihF, const float* __restrict__ bhhF,
                            const float* __restrict__ bihB, const float* __restrict__ bhhB,
                            const float* __restrict__ WihF, const float* __restrict__ WihB,
                            const float* __restrict__ S1W,
                            float* __restrict__ biasf, float* __restrict__ biasb,
                            float* __restrict__ wihFr, float* __restrict__ wihBr,
                            float* __restrict__ s1wr, int* __restrict__ bars)
{
    int gid = blockIdx.x * 256 + threadIdx.x;   // 0..262143
    wihFr[gid] = rndtf(WihF[gid]);
    wihBr[gid] = rndtf(WihB[gid]);
    s1wr [gid] = rndtf(S1W [gid]);
    if (gid < G4) {
        biasf[gid] = bihF[gid] + bhhF[gid];
        biasb[gid] = bihB[gid] + bhhB[gid];
    }
    if (gid < 12) bars[gid] = 0;
}

// ---------------------------------------------------------------------------
// Embedding gather (tf32-rounded output — X is a GEMM operand)
// ---------------------------------------------------------------------------
__global__ void embed_kernel(const int* __restrict__ tq, const int* __restrict__ tc,
                             const int* __restrict__ tc2,
                             const float4* __restrict__ emb, float4* __restrict__ X)
{
    int gid = blockIdx.x * 256 + threadIdx.x;      // 3145728 total
    int c4  = gid & 63;
    int row = gid >> 6;
    int seq = row / MBS;
    int rb  = row - seq * MBS;
    int b   = rb >> 7, s = rb & 127;
    const int* tok = (seq == 0) ? tq : ((seq == 1) ? tc : tc2);
    int t = tok[s * BB + b];
    float4 v = emb[(size_t)t * 64 + c4];
    v.x = rndtf(v.x); v.y = rndtf(v.y); v.z = rndtf(v.z); v.w = rndtf(v.w);
    X[(size_t)row * 64 + c4] = v;
}

// ---------------------------------------------------------------------------
// tf32 tensor-core GEMM, NT form, 2-stage cp.async pipeline (dynamic smem).
// Operands are PRE-ROUNDED to tf32 in global memory, so feeding raw bits to
// the mma (truncation) is numerically identical to rna conversion.
// Tile 128x128, K-chunk 32, 8 warps 4(m)x2(n), warp tile 32x64.
// EPI: 0=none, 1=+bias[n], 2=rndtf(tanh(x+bias[n]))  [Ct is a GEMM operand]
// ---------------------------------------------------------------------------
template<int EPI>
__global__ __launch_bounds__(256) void tgemm_kernel(
    int M, int N, int K,
    const float* __restrict__ A, int lda, size_t sA,
    const float* __restrict__ B, int ldb, size_t sB,
    float* __restrict__ C, int ldc, size_t sC,
    const float* __restrict__ bias)
{
    extern __shared__ unsigned tsm[];
    unsigned* As[2] = { tsm,              tsm + TG_BUF };
    unsigned* Bs[2] = { tsm + 2 * TG_BUF, tsm + 3 * TG_BUF };

    int bx = blockIdx.x, by = blockIdx.y, bz = blockIdx.z;
    const float* Ap = A + (size_t)bz * sA + (size_t)by * 128 * lda;
    const float* Bp = B + (size_t)bz * sB + (size_t)bx * 128 * ldb;
    float* Cp = C + (size_t)bz * sC + (size_t)by * 128 * ldc + (size_t)bx * 128;

    int tid = threadIdx.x, lane = tid & 31, warp = tid >> 5;
    int wm = warp & 3, wn = warp >> 2;
    int ly = lane >> 2, lx = lane & 3;

    int cpRow = tid >> 3, cpC4 = (tid & 7) * 4;   // thread copies rows cpRow+32i

    float acc[2][8][4];
#pragma unroll
    for (int im = 0; im < 2; im++)
#pragma unroll
        for (int nt = 0; nt < 8; nt++)
#pragma unroll
            for (int j = 0; j < 4; j++) acc[im][nt][j] = 0.f;

    int NC = K >> 5;   // chunks of 32

    auto issue = [&](int kc, int b) {
        int k0 = kc * 32;
#pragma unroll
        for (int i = 0; i < 4; i++) {
            int row = cpRow + 32 * i;
            unsigned sa = smem_u32(&As[b][row * 36 + cpC4]);
            asm volatile("cp.async.cg.shared.global [%0], [%1], 16;"
                         :: "r"(sa), "l"(Ap + (size_t)row * lda + k0 + cpC4));
            unsigned sb = smem_u32(&Bs[b][row * 36 + cpC4]);
            asm volatile("cp.async.cg.shared.global [%0], [%1], 16;"
                         :: "r"(sb), "l"(Bp + (size_t)row * ldb + k0 + cpC4));
        }
        asm volatile("cp.async.commit_group;");
    };

    issue(0, 0);
    for (int kc = 0; kc < NC; kc++) {
        int b = kc & 1;
        if (kc + 1 < NC) {
            issue(kc + 1, b ^ 1);
            asm volatile("cp.async.wait_group 1;");
        } else {
            asm volatile("cp.async.wait_group 0;");
        }
        __syncthreads();

        const unsigned* Ab = As[b];
        const unsigned* Bb = Bs[b];
#pragma unroll
        for (int kk = 0; kk < 4; kk++) {
            int k8 = kk * 8;
            unsigned a[2][4];
#pragma unroll
            for (int im = 0; im < 2; im++) {
                int rb = wm * 32 + im * 16;
                a[im][0] = Ab[(rb + ly) * 36 + k8 + lx];
                a[im][1] = Ab[(rb + ly + 8) * 36 + k8 + lx];
                a[im][2] = Ab[(rb + ly) * 36 + k8 + lx + 4];
                a[im][3] = Ab[(rb + ly + 8) * 36 + k8 + lx + 4];
            }
#pragma unroll
            for (int nt = 0; nt < 8; nt++) {
                int n = wn * 64 + nt * 8 + ly;
                unsigned b0 = Bb[n * 36 + k8 + lx];
                unsigned b1 = Bb[n * 36 + k8 + lx + 4];
                mma_tf32(acc[0][nt], a[0], b0, b1);
                mma_tf32(acc[1][nt], a[1], b0, b1);
            }
        }
        __syncthreads();
    }

#pragma unroll
    for (int im = 0; im < 2; im++) {
#pragma unroll
        for (int nt = 0; nt < 8; nt++) {
            int n0 = wn * 64 + nt * 8 + lx * 2;
            int r0 = wm * 32 + im * 16 + ly;
            float2 v0 = make_float2(acc[im][nt][0], acc[im][nt][1]);
            float2 v1 = make_float2(acc[im][nt][2], acc[im][nt][3]);
            if constexpr (EPI >= 1) {
                float b0v = bias[bx * 128 + n0], b1v = bias[bx * 128 + n0 + 1];
                v0.x += b0v; v0.y += b1v; v1.x += b0v; v1.y += b1v;
            }
            if constexpr (EPI == 2) {
                v0.x = rndtf(tanhf(v0.x)); v0.y = rndtf(tanhf(v0.y));
                v1.x = rndtf(tanhf(v1.x)); v1.y = rndtf(tanhf(v1.y));
            }
            *reinterpret_cast<float2*>(&Cp[(size_t)r0 * ldc + n0]) = v0;
            *reinterpret_cast<float2*>(&Cp[(size_t)(r0 + 8) * ldc + n0]) = v1;
        }
    }
}

// ---------------------------------------------------------------------------
// Batched transpose (tf32-rounded output — both uses feed GEMM B operands)
// ---------------------------------------------------------------------------
__global__ void transpose_kernel(const float* __restrict__ in, float* __restrict__ out)
{
    __shared__ float tile[32][33];
    int b = blockIdx.z;
    const float* ip = in + (size_t)b * SQ * D2;
    float* op = out + (size_t)b * SQ * D2;
    int c0 = blockIdx.x * 32, r0 = blockIdx.y * 32;
    int x = threadIdx.x, y = threadIdx.y;
#pragma unroll
    for (int j = 0; j < 32; j += 8)
        tile[y + j][x] = ip[(size_t)(r0 + y + j) * D2 + c0 + x];
    __syncthreads();
#pragma unroll
    for (int j = 0; j < 32; j += 8)
        op[(size_t)(c0 + y + j) * SQ + r0 + x] = rndtf(tile[x][y + j]);
}

// ---------------------------------------------------------------------------
// LSTM recurrence — R4 verified version; Y writes now tf32-rounded
// (its own reload applies f2tf anyway -> identity; downstream GEMMs get
//  exactly what R4's rna-converting loads produced).
// ---------------------------------------------------------------------------
__global__ __launch_bounds__(256) void lstm_mma_kernel(
    const float* __restrict__ xpreF, const float* __restrict__ xpreB,
    const float* __restrict__ WhhF, const float* __restrict__ WhhB,
    const float* __restrict__ h_q, const float* __restrict__ c_q,
    const float* __restrict__ h_c, const float* __restrict__ c_c,
    const float* __restrict__ h_c2, const float* __restrict__ c_c2,
    float* __restrict__ Y, int* __restrict__ bars)
{
    extern __shared__ unsigned sm[];
    unsigned* smW = sm;                  // [128][WPAD] tf32 weights
    unsigned* smH = sm + 128 * WPAD;     // [64][HPAD] tf32 h  (aliased by G)
    float*    smG = (float*)smH;         // [64][GPAD] fp32 gates

    int bx  = blockIdx.x;
    int sd  = bx >> 4;
    int rem = bx & 15;
    int bg  = rem >> 3;
    int gg  = rem & 7;
    int seq = sd >> 1, dir = sd & 1;
    int grp = sd * 2 + bg;

    int tid  = threadIdx.x;
    int lane = tid & 31, warp = tid >> 5;
    int ly = lane >> 2, lx = lane & 3;
    int mt = warp & 3;
    int nh = warp >> 2;

    const float* xpre = (dir ? xpreB : xpreF) + (size_t)seq * MBS * G4;
    const float* Whh  = dir ? WhhB : WhhF;
    const float* h0p  = (seq == 0) ? h_q : ((seq == 1) ? h_c : h_c2);
    const float* c0p  = (seq == 0) ? c_q : ((seq == 1) ? c_c : c_c2);

    for (int i = tid; i < 128 * 256; i += 256) {
        int r = i >> 8, c = i & 255;
        int g = r >> 5, u_ = r & 31;
        smW[r * WPAD + c] = f2tf(Whh[(size_t)(g * 256 + gg * 32 + u_) * 256 + c]);
    }
    for (int i = tid; i < 64 * 64; i += 256) {
        int r = i >> 6, c4 = (i & 63) * 4;
        float4 v = *(const float4*)&h0p[((size_t)(dir * BB + bg * 64 + r)) * HH + c4];
        uint4 w; w.x = f2tf(v.x); w.y = f2tf(v.y); w.z = f2tf(v.z); w.w = f2tf(v.w);
        *(uint4*)&smH[r * HPAD + c4] = w;
    }
    int u  = tid & 31;
    int mb = warp * 8;
    float cst[8];
#pragma unroll
    for (int p = 0; p < 8; p++)
        cst[p] = c0p[((size_t)(dir * BB + bg * 64 + mb + p)) * HH + gg * 32 + u];
    __syncthreads();

    volatile int* vb = (volatile int*)(bars + grp);

    for (int t = 0; t < SQ; t++) {
        int te = dir ? (SQ - 1 - t) : t;

        float acc[8][4];
#pragma unroll
        for (int n = 0; n < 8; n++)
#pragma unroll
            for (int j = 0; j < 4; j++) acc[n][j] = 0.f;

        const unsigned* hA = smH + (mt * 16 + ly) * HPAD + lx;
#pragma unroll 4
        for (int k0 = 0; k0 < 256; k0 += 8) {
            unsigned a[4];
            a[0] = hA[k0];
            a[1] = hA[k0 + 8 * HPAD];
            a[2] = hA[k0 + 4];
            a[3] = hA[k0 + 8 * HPAD + 4];
#pragma unroll
            for (int nt = 0; nt < 8; nt++) {
                const unsigned* wB = smW + (nh * 64 + nt * 8 + ly) * WPAD + k0 + lx;
                mma_tf32(acc[nt], a, wB[0], wB[4]);
            }
        }
        __syncthreads();

#pragma unroll
        for (int nt = 0; nt < 8; nt++) {
            int n0 = nh * 64 + nt * 8 + lx * 2;
            int r0 = mt * 16 + ly;
            *(float2*)&smG[r0 * GPAD + n0]       = make_float2(acc[nt][0], acc[nt][1]);
            *(float2*)&smG[(r0 + 8) * GPAD + n0] = make_float2(acc[nt][2], acc[nt][3]);
        }
        __syncthreads();

#pragma unroll
        for (int p = 0; p < 8; p++) {
            int m = mb + p;
            const float* xp = &xpre[(((size_t)(bg * 64 + m)) * SQ + te) * G4 + gg * 32 + u];
            float gi = smG[m * GPAD +      u] + xp[0];
            float gf = smG[m * GPAD + 32 + u] + xp[256];
            float gc = smG[m * GPAD + 64 + u] + xp[512];
            float go = smG[m * GPAD + 96 + u] + xp[768];
            float i_ = 1.f / (1.f + __expf(-gi));
            float f_ = 1.f / (1.f + __expf(-gf));
            float g_ = tanhf(gc);
            float o_ = 1.f / (1.f + __expf(-go));
            float c  = f_ * cst[p] + i_ * g_;
            cst[p] = c;
            float h = rndtf(o_ * tanhf(c));
            Y[(((size_t)(seq * BB + bg * 64 + m)) * SQ + te) * D2 + dir * HH + gg * 32 + u] = h;
        }

        __threadfence();
        __syncthreads();
        if (tid == 0) {
            atomicAdd(bars + grp, 1);
            int target = 8 * (t + 1);
            while (*vb < target) { }
            __threadfence();
        }
        __syncthreads();

        for (int i = tid; i < 64 * 64; i += 256) {
            int r = i >> 6, c4 = (i & 63) * 4;
            float4 v = __ldcg((const float4*)&Y[
                (((size_t)(seq * BB + bg * 64 + r)) * SQ + te) * D2 + dir * HH + c4]);
            uint4 w; w.x = f2tf(v.x); w.y = f2tf(v.y); w.z = f2tf(v.z); w.w = f2tf(v.w);
            *(uint4*)&smH[r * HPAD + c4] = w;
        }
        __syncthreads();
    }
}

// ---------------------------------------------------------------------------
// Softmax kernels (tf32-rounded outputs — AQ/AC are GEMM A operands)
// ---------------------------------------------------------------------------
__global__ void row_softmax(const float* __restrict__ Hm, float* __restrict__ AQ)
{
    int warp = (blockIdx.x * blockDim.x + threadIdx.x) >> 5;
    int lane = threadIdx.x & 31;
    const float* base = Hm + (size_t)warp * SQ;
    float v[4], m = -1e30f;
#pragma unroll
    for (int u = 0; u < 4; u++) { v[u] = base[lane + 32 * u]; m = fmaxf(m, v[u]); }
#pragma unroll
    for (int o = 16; o > 0; o >>= 1) m = fmaxf(m, __shfl_xor_sync(0xffffffffu, m, o));
    float s = 0.f;
#pragma unroll
    for (int u = 0; u < 4; u++) { v[u] = __expf(v[u] - m); s += v[u]; }
#pragma unroll
    for (int o = 16; o > 0; o >>= 1) s += __shfl_xor_sync(0xffffffffu, s, o);
    float inv = 1.f / s;
    float* out = AQ + (size_t)warp * SQ;
#pragma unroll
    for (int u = 0; u < 4; u++) out[lane + 32 * u] = rndtf(v[u] * inv);
}

__global__ void col_softmax(const float* __restrict__ Hm, float* __restrict__ AC)
{
    int warp = (blockIdx.x * blockDim.x + threadIdx.x) >> 5;
    int lane = threadIdx.x & 31;
    int b = warp >> 7, s = warp & 127;
    const float* base = Hm + (size_t)b * SQ * SQ + s;
    float v[4], m = -1e30f;
#pragma unroll
    for (int u = 0; u < 4; u++) { v[u] = base[(size_t)(lane + 32 * u) * SQ]; m = fmaxf(m, v[u]); }
#pragma unroll
    for (int o = 16; o > 0; o >>= 1) m = fmaxf(m, __shfl_xor_sync(0xffffffffu, m, o));
    float sm = 0.f;
#pragma unroll
    for (int u = 0; u < 4; u++) { v[u] = __expf(v[u] - m); sm += v[u]; }
#pragma unroll
    for (int o = 16; o > 0; o >>= 1) sm += __shfl_xor_sync(0xffffffffu, sm, o);
    float inv = 1.f / sm;
    float* out = AC + (size_t)b * SQ * SQ + (size_t)s * SQ;
#pragma unroll
    for (int u = 0; u < 4; u++) out[lane + 32 * u] = rndtf(v[u] * inv);
}

// ---------------------------------------------------------------------------
// Host-side GEMM dispatch (dynamic smem)
// ---------------------------------------------------------------------------
static void run_tgemm(int epi, int M, int N, int K,
                      const float* A, int lda, size_t sA,
                      const float* B, int ldb, size_t sB,
                      float* C, int ldc, size_t sC,
                      const float* bias, int batch)
{
    dim3 grid(N / 128, M / 128, batch), block(256);
    size_t sh = TGEMM_SMEM_BYTES;
    if (epi == 0)      tgemm_kernel<0><<<grid, block, sh>>>(M, N, K, A, lda, sA, B, ldb, sB, C, ldc, sC, bias);
    else if (epi == 1) tgemm_kernel<1><<<grid, block, sh>>>(M, N, K, A, lda, sA, B, ldb, sB, C, ldc, sC, bias);
    else               tgemm_kernel<2><<<grid, block, sh>>>(M, N, K, A, lda, sA, B, ldb, sB, C, ldc, sC, bias);
}

// ---------------------------------------------------------------------------
// kernel_launch
// ---------------------------------------------------------------------------
extern "C" void kernel_launch(void* const* d_in, const int* in_sizes, int n_in,
                              void* d_out, int out_size)
{
    (void)in_sizes; (void)n_in; (void)out_size;
    const int*   inQ   = (const int*)d_in[1];
    const int*   inC   = (const int*)d_in[2];
    const int*   inC2  = (const int*)d_in[3];
    const float* hidQ  = (const float*)d_in[4];
    const float* celQ  = (const float*)d_in[5];
    const float* hidC  = (const float*)d_in[6];
    const float* celC  = (const float*)d_in[7];
    const float* hidC2 = (const float*)d_in[8];
    const float* celC2 = (const float*)d_in[9];
    const float* emb   = (const float*)d_in[10];
    const float* WihF  = (const float*)d_in[11];
    const float* WhhF  = (const float*)d_in[12];
    const float* bihF  = (const float*)d_in[13];
    const float* bhhF  = (const float*)d_in[14];
    const float* WihB  = (const float*)d_in[15];
    const float* WhhB  = (const float*)d_in[16];
    const float* bihB  = (const float*)d_in[17];
    const float* bhhB  = (const float*)d_in[18];
    const float* S1W   = (const float*)d_in[19];
    const float* S1b   = (const float*)d_in[20];
    float* out = (float*)d_out;

    void *pX, *pXpF, *pXpB, *pWFr, *pWBr, *pS1r, *pBf, *pBb, *pY, *pCt,
         *pYqT, *pMQT, *pHm, *pAQ, *pAC, *pBar;
    cudaGetSymbolAddress(&pX,   g_X);
    cudaGetSymbolAddress(&pXpF, g_XpreF);
    cudaGetSymbolAddress(&pXpB, g_XpreB);
    cudaGetSymbolAddress(&pWFr, g_WihFr);
    cudaGetSymbolAddress(&pWBr, g_WihBr);
    cudaGetSymbolAddress(&pS1r, g_S1Wr);
    cudaGetSymbolAddress(&pBf,  g_biasf);
    cudaGetSymbolAddress(&pBb,  g_biasb);
    cudaGetSymbolAddress(&pY,   g_Y);
    cudaGetSymbolAddress(&pCt,  g_Ct);
    cudaGetSymbolAddress(&pYqT, g_YqT);
    cudaGetSymbolAddress(&pMQT, g_MQT);
    cudaGetSymbolAddress(&pHm,  g_Hm);
    cudaGetSymbolAddress(&pAQ,  g_AQ);
    cudaGetSymbolAddress(&pAC,  g_AC);
    cudaGetSymbolAddress(&pBar, g_bar);
    float* X    = (float*)pX;
    float* XpF  = (float*)pXpF;
    float* XpB  = (float*)pXpB;
    float* WFr  = (float*)pWFr;
    float* WBr  = (float*)pWBr;
    float* S1r  = (float*)pS1r;
    float* Bf   = (float*)pBf;
    float* Bb   = (float*)pBb;
    float* Y    = (float*)pY;
    float* Ct   = (float*)pCt;
    float* YqT  = (float*)pYqT;
    float* MQT  = (float*)pMQT;
    float* Hm   = (float*)pHm;
    float* AQ   = (float*)pAQ;
    float* AC   = (float*)pAC;
    int*   bars = (int*)pBar;

    cudaFuncSetAttribute(lstm_mma_kernel,
                         cudaFuncAttributeMaxDynamicSharedMemorySize,
                         LSTM_SMEM_BYTES);
    cudaFuncSetAttribute(tgemm_kernel<0>,
                         cudaFuncAttributeMaxDynamicSharedMemorySize,
                         TGEMM_SMEM_BYTES);
    cudaFuncSetAttribute(tgemm_kernel<1>,
                         cudaFuncAttributeMaxDynamicSharedMemorySize,
                         TGEMM_SMEM_BYTES);
    cudaFuncSetAttribute(tgemm_kernel<2>,
                         cudaFuncAttributeMaxDynamicSharedMemorySize,
                         TGEMM_SMEM_BYTES);

    // 1. prep: bias fold, barrier reset, rounded weight copies
    prep_kernel<<<1024, 256>>>(bihF, bhhF, bihB, bhhB, WihF, WihB, S1W,
                               Bf, Bb, WFr, WBr, S1r, bars);

    // 2. embedding gather (rounded)
    embed_kernel<<<12288, 256>>>(inQ, inC, inC2, (const float4*)emb, (float4*)X);

    // 3. input GEMMs: Xpre = X @ Wih^T + (bih+bhh)
    run_tgemm(1, MX, G4, EE, X, EE, 0, WFr, EE, 0, XpF, G4, 0, Bf, 1);
    run_tgemm(1, MX, G4, EE, X, EE, 0, WBr, EE, 0, XpB, G4, 0, Bb, 1);

    // 4. recurrence (tensor-core, 96 resident CTAs, global-atomic exchange)
    lstm_mma_kernel<<<96, 256, LSTM_SMEM_BYTES>>>(
        XpF, XpB, WhhF, WhhB,
        hidQ, celQ, hidC, celC, hidC2, celC2, Y, bars);

    // 5. Ct = rndtf(tanh(Y_c @ S1_W^T + S1_b))
    run_tgemm(2, MBS, D2, D2, Y + (size_t)1 * MBS * D2, D2, 0,
              S1r, D2, 0, Ct, D2, 0, S1b, 1);
    run_tgemm(2, MBS, D2, D2, Y + (size_t)2 * MBS * D2, D2, 0,
              S1r, D2, 0, Ct + (size_t)MBS * D2, D2, 0, S1b, 1);

    // 5b. Yq^T for the MQ GEMM's B operand
    {
        dim3 tg(D2 / 32, SQ / 32, BB), tb(32, 8);
        transpose_kernel<<<tg, tb>>>(Y, YqT);
    }

    // 6. attention for pairs (Q,C) and (Q,C2)
    for (int p = 0; p < 2; p++) {
        run_tgemm(0, SQ, SQ, D2,
                  Y, D2, (size_t)SQ * D2,
                  Ct + (size_t)p * MBS * D2, D2, (size_t)SQ * D2,
                  Hm, SQ, (size_t)SQ * SQ, nullptr, BB);
        row_softmax<<<2048, 256>>>(Hm, AQ);
        col_softmax<<<2048, 256>>>(Hm, AC);
        float* outMQ = out + (size_t)(2 * p) * OUTREG;
        float* outMC = out + (size_t)(2 * p + 1) * OUTREG;
        run_tgemm(0, SQ, D2, SQ,
                  AQ, SQ, (size_t)SQ * SQ,
                  YqT, SQ, (size_t)SQ * D2,
                  outMQ, D2, (size_t)SQ * D2, nullptr, BB);
        {
            dim3 tg(D2 / 32, SQ / 32, BB), tb(32, 8);
            transpose_kernel<<<tg, tb>>>(outMQ, MQT);
        }
        run_tgemm(0, SQ, D2, SQ,
                  AC, SQ, (size_t)SQ * SQ,
                  MQT, SQ, (size_t)SQ * D2,
                  outMC, D2, (size_t)SQ * D2, nullptr, BB);
    }
}

// round 10
// speedup vs baseline: 1.4834x; 1.0605x over previous
#include <cuda_runtime.h>
#include <cuda_bf16.h>
#include <cstdint>
#include <math.h>

// ---------------------------------------------------------------------------
// Problem constants
// ---------------------------------------------------------------------------
#define SQ   128            // seq len
#define BB   128            // batch
#define EE   256            // embed dim
#define HH   256            // hidden
#define G4   1024           // 4*H
#define D2   512            // 2*H
#define MBS  (BB*SQ)        // 16384
#define MX   (3*MBS)        // 49152 rows of X
#define OUTREG (BB*SQ*D2)   // 8388608 floats per output tensor

// LSTM-mma geometry (R4 verified)
#define WPAD 260
#define HPAD 260
#define GPAD 132
#define LSTM_SMEM_BYTES ((128*WPAD + 64*HPAD) * 4)   // 199,680 B

// tgemm dynamic smem: 2 buffers x (A + B) x 128*36 words
#define TG_BUF (128 * 36)
#define TGEMM_SMEM_BYTES (4 * TG_BUF * 4)            // 73,728 B

// ---------------------------------------------------------------------------
// Device scratch
// ---------------------------------------------------------------------------
__device__ float g_X    [3*MBS*EE];     //  50 MB  embedded inputs (tf32-rounded)
__device__ float g_XpreF[3*MBS*G4];     // 201 MB  X@Wih_f^T + bias_f  (fp32)
__device__ float g_XpreB[3*MBS*G4];     // 201 MB
__device__ float g_WihFr[G4*EE];        //   1 MB  tf32-rounded Wih_f
__device__ float g_WihBr[G4*EE];        //   1 MB  tf32-rounded Wih_b
__device__ float g_S1Wr [D2*D2];        //   1 MB  tf32-rounded S1_W
__device__ float g_biasf[G4];
__device__ float g_biasb[G4];
__device__ float g_Y    [3*MBS*D2];     // 100 MB  BiLSTM outputs (tf32-rounded)
__device__ float g_Ct   [2*MBS*D2];     //  67 MB  tanh(S1(C)) (tf32-rounded)
__device__ float g_YqT  [MBS*D2];       //  33 MB  transpose of Q stream (rounded)
__device__ float g_MQT  [MBS*D2];       //  33 MB  transpose of MQ (rounded)
__device__ float g_Hm   [BB*SQ*SQ];     // 8.4 MB  logits (fp32)
__device__ float g_AQ   [BB*SQ*SQ];     //          softmax (tf32-rounded)
__device__ float g_AC   [BB*SQ*SQ];
__device__ int   g_bar  [12];           // barrier counters (6 streams x 2 halves)

// ---------------------------------------------------------------------------
// tf32 helpers
// ---------------------------------------------------------------------------
__device__ __forceinline__ unsigned f2tf(float f) {
    unsigned r;
    asm("cvt.rna.tf32.f32 %0, %1;" : "=r"(r) : "f"(f));
    return r;
}
__device__ __forceinline__ float rndtf(float f) {     // rna tf32 round, kept in fp32
    return __uint_as_float(f2tf(f));
}
__device__ __forceinline__ void mma_tf32(float* d, const unsigned a[4],
                                         unsigned b0, unsigned b1) {
    asm volatile(
        "mma.sync.aligned.m16n8k8.row.col.f32.tf32.tf32.f32 "
        "{%0,%1,%2,%3},{%4,%5,%6,%7},{%8,%9},{%0,%1,%2,%3};"
        : "+f"(d[0]), "+f"(d[1]), "+f"(d[2]), "+f"(d[3])
        : "r"(a[0]), "r"(a[1]), "r"(a[2]), "r"(a[3]), "r"(b0), "r"(b1));
}
__device__ __forceinline__ unsigned smem_u32(const void* p) {
    unsigned a;
    asm("{ .reg .u64 t; cvta.to.shared.u64 t, %1; cvt.u32.u64 %0, t; }"
        : "=r"(a) : "l"(p));
    return a;
}
__device__ __forceinline__ void prefetchL2(const void* p) {
    asm volatile("prefetch.global.L2 [%0];" :: "l"(p));
}

// ---------------------------------------------------------------------------
// Prep: bias fold, barrier reset, tf32-rounded weight copies. (Idempotent —
// launched twice to shift the ncu -s5 capture window onto lstm_mma_kernel.)
// ---------------------------------------------------------------------------
__global__ void prep_kernel(const float* __restrict__ bihF, const float* __restrict__ bhhF,
                            const float* __restrict__ bihB, const float* __restrict__ bhhB,
                            const float* __restrict__ WihF, const float* __restrict__ WihB,
                            const float* __restrict__ S1W,
                            float* __restrict__ biasf, float* __restrict__ biasb,
                            float* __restrict__ wihFr, float* __restrict__ wihBr,
                            float* __restrict__ s1wr, int* __restrict__ bars)
{
    int gid = blockIdx.x * 256 + threadIdx.x;   // 0..262143
    wihFr[gid] = rndtf(WihF[gid]);
    wihBr[gid] = rndtf(WihB[gid]);
    s1wr [gid] = rndtf(S1W [gid]);
    if (gid < G4) {
        biasf[gid] = bihF[gid] + bhhF[gid];
        biasb[gid] = bihB[gid] + bhhB[gid];
    }
    if (gid < 12) bars[gid] = 0;
}

// ---------------------------------------------------------------------------
// Embedding gather (tf32-rounded output — X is a GEMM operand)
// ---------------------------------------------------------------------------
__global__ void embed_kernel(const int* __restrict__ tq, const int* __restrict__ tc,
                             const int* __restrict__ tc2,
                             const float4* __restrict__ emb, float4* __restrict__ X)
{
    int gid = blockIdx.x * 256 + threadIdx.x;      // 3145728 total
    int c4  = gid & 63;
    int row = gid >> 6;
    int seq = row / MBS;
    int rb  = row - seq * MBS;
    int b   = rb >> 7, s = rb & 127;
    const int* tok = (seq == 0) ? tq : ((seq == 1) ? tc : tc2);
    int t = tok[s * BB + b];
    float4 v = emb[(size_t)t * 64 + c4];
    v.x = rndtf(v.x); v.y = rndtf(v.y); v.z = rndtf(v.z); v.w = rndtf(v.w);
    X[(size_t)row * 64 + c4] = v;
}

// ---------------------------------------------------------------------------
// tf32 tensor-core GEMM, NT form, 2-stage cp.async pipeline (dynamic smem).
// Operands PRE-ROUNDED to tf32 -> raw-bit feed == rna conversion.
// ---------------------------------------------------------------------------
template<int EPI>   // 0=none, 1=+bias[n], 2=rndtf(tanh(x+bias[n]))
__global__ __launch_bounds__(256) void tgemm_kernel(
    int M, int N, int K,
    const float* __restrict__ A, int lda, size_t sA,
    const float* __restrict__ B, int ldb, size_t sB,
    float* __restrict__ C, int ldc, size_t sC,
    const float* __restrict__ bias)
{
    extern __shared__ unsigned tsm[];
    unsigned* As[2] = { tsm,              tsm + TG_BUF };
    unsigned* Bs[2] = { tsm + 2 * TG_BUF, tsm + 3 * TG_BUF };

    int bx = blockIdx.x, by = blockIdx.y, bz = blockIdx.z;
    const float* Ap = A + (size_t)bz * sA + (size_t)by * 128 * lda;
    const float* Bp = B + (size_t)bz * sB + (size_t)bx * 128 * ldb;
    float* Cp = C + (size_t)bz * sC + (size_t)by * 128 * ldc + (size_t)bx * 128;

    int tid = threadIdx.x, lane = tid & 31, warp = tid >> 5;
    int wm = warp & 3, wn = warp >> 2;
    int ly = lane >> 2, lx = lane & 3;

    int cpRow = tid >> 3, cpC4 = (tid & 7) * 4;

    float acc[2][8][4];
#pragma unroll
    for (int im = 0; im < 2; im++)
#pragma unroll
        for (int nt = 0; nt < 8; nt++)
#pragma unroll
            for (int j = 0; j < 4; j++) acc[im][nt][j] = 0.f;

    int NC = K >> 5;

    auto issue = [&](int kc, int b) {
        int k0 = kc * 32;
#pragma unroll
        for (int i = 0; i < 4; i++) {
            int row = cpRow + 32 * i;
            unsigned sa = smem_u32(&As[b][row * 36 + cpC4]);
            asm volatile("cp.async.cg.shared.global [%0], [%1], 16;"
                         :: "r"(sa), "l"(Ap + (size_t)row * lda + k0 + cpC4));
            unsigned sb = smem_u32(&Bs[b][row * 36 + cpC4]);
            asm volatile("cp.async.cg.shared.global [%0], [%1], 16;"
                         :: "r"(sb), "l"(Bp + (size_t)row * ldb + k0 + cpC4));
        }
        asm volatile("cp.async.commit_group;");
    };

    issue(0, 0);
    for (int kc = 0; kc < NC; kc++) {
        int b = kc & 1;
        if (kc + 1 < NC) {
            issue(kc + 1, b ^ 1);
            asm volatile("cp.async.wait_group 1;");
        } else {
            asm volatile("cp.async.wait_group 0;");
        }
        __syncthreads();

        const unsigned* Ab = As[b];
        const unsigned* Bb = Bs[b];
#pragma unroll
        for (int kk = 0; kk < 4; kk++) {
            int k8 = kk * 8;
            unsigned a[2][4];
#pragma unroll
            for (int im = 0; im < 2; im++) {
                int rb = wm * 32 + im * 16;
                a[im][0] = Ab[(rb + ly) * 36 + k8 + lx];
                a[im][1] = Ab[(rb + ly + 8) * 36 + k8 + lx];
                a[im][2] = Ab[(rb + ly) * 36 + k8 + lx + 4];
                a[im][3] = Ab[(rb + ly + 8) * 36 + k8 + lx + 4];
            }
#pragma unroll
            for (int nt = 0; nt < 8; nt++) {
                int n = wn * 64 + nt * 8 + ly;
                unsigned b0 = Bb[n * 36 + k8 + lx];
                unsigned b1 = Bb[n * 36 + k8 + lx + 4];
                mma_tf32(acc[0][nt], a[0], b0, b1);
                mma_tf32(acc[1][nt], a[1], b0, b1);
            }
        }
        __syncthreads();
    }

#pragma unroll
    for (int im = 0; im < 2; im++) {
#pragma unroll
        for (int nt = 0; nt < 8; nt++) {
            int n0 = wn * 64 + nt * 8 + lx * 2;
            int r0 = wm * 32 + im * 16 + ly;
            float2 v0 = make_float2(acc[im][nt][0], acc[im][nt][1]);
            float2 v1 = make_float2(acc[im][nt][2], acc[im][nt][3]);
            if constexpr (EPI >= 1) {
                float b0v = bias[bx * 128 + n0], b1v = bias[bx * 128 + n0 + 1];
                v0.x += b0v; v0.y += b1v; v1.x += b0v; v1.y += b1v;
            }
            if constexpr (EPI == 2) {
                v0.x = rndtf(tanhf(v0.x)); v0.y = rndtf(tanhf(v0.y));
                v1.x = rndtf(tanhf(v1.x)); v1.y = rndtf(tanhf(v1.y));
            }
            *reinterpret_cast<float2*>(&Cp[(size_t)r0 * ldc + n0]) = v0;
            *reinterpret_cast<float2*>(&Cp[(size_t)(r0 + 8) * ldc + n0]) = v1;
        }
    }
}

// ---------------------------------------------------------------------------
// Batched transpose (tf32-rounded output)
// ---------------------------------------------------------------------------
__global__ void transpose_kernel(const float* __restrict__ in, float* __restrict__ out)
{
    __shared__ float tile[32][33];
    int b = blockIdx.z;
    const float* ip = in + (size_t)b * SQ * D2;
    float* op = out + (size_t)b * SQ * D2;
    int c0 = blockIdx.x * 32, r0 = blockIdx.y * 32;
    int x = threadIdx.x, y = threadIdx.y;
#pragma unroll
    for (int j = 0; j < 32; j += 8)
        tile[y + j][x] = ip[(size_t)(r0 + y + j) * D2 + c0 + x];
    __syncthreads();
#pragma unroll
    for (int j = 0; j < 32; j += 8)
        op[(size_t)(c0 + y + j) * SQ + r0 + x] = rndtf(tile[x][y + j]);
}

// ---------------------------------------------------------------------------
// LSTM recurrence — R4-verified core + two critical-path cuts:
//  (1) prefetch.global.L2 of this step's xpre values during the MMA phase
//  (2) own-h chunk written to smH from registers; reload skips it
// ---------------------------------------------------------------------------
__global__ __launch_bounds__(256) void lstm_mma_kernel(
    const float* __restrict__ xpreF, const float* __restrict__ xpreB,
    const float* __restrict__ WhhF, const float* __restrict__ WhhB,
    const float* __restrict__ h_q, const float* __restrict__ c_q,
    const float* __restrict__ h_c, const float* __restrict__ c_c,
    const float* __restrict__ h_c2, const float* __restrict__ c_c2,
    float* __restrict__ Y, int* __restrict__ bars)
{
    extern __shared__ unsigned sm[];
    unsigned* smW = sm;                  // [128][WPAD] tf32 weights
    unsigned* smH = sm + 128 * WPAD;     // [64][HPAD] tf32 h  (aliased by G)
    float*    smG = (float*)smH;         // [64][GPAD] fp32 gates

    int bx  = blockIdx.x;
    int sd  = bx >> 4;
    int rem = bx & 15;
    int bg  = rem >> 3;
    int gg  = rem & 7;
    int seq = sd >> 1, dir = sd & 1;
    int grp = sd * 2 + bg;

    int tid  = threadIdx.x;
    int lane = tid & 31, warp = tid >> 5;
    int ly = lane >> 2, lx = lane & 3;
    int mt = warp & 3;
    int nh = warp >> 2;

    const float* xpre = (dir ? xpreB : xpreF) + (size_t)seq * MBS * G4;
    const float* Whh  = dir ? WhhB : WhhF;
    const float* h0p  = (seq == 0) ? h_q : ((seq == 1) ? h_c : h_c2);
    const float* c0p  = (seq == 0) ? c_q : ((seq == 1) ? c_c : c_c2);

    for (int i = tid; i < 128 * 256; i += 256) {
        int r = i >> 8, c = i & 255;
        int g = r >> 5, u_ = r & 31;
        smW[r * WPAD + c] = f2tf(Whh[(size_t)(g * 256 + gg * 32 + u_) * 256 + c]);
    }
    for (int i = tid; i < 64 * 64; i += 256) {
        int r = i >> 6, c4 = (i & 63) * 4;
        float4 v = *(const float4*)&h0p[((size_t)(dir * BB + bg * 64 + r)) * HH + c4];
        uint4 w; w.x = f2tf(v.x); w.y = f2tf(v.y); w.z = f2tf(v.z); w.w = f2tf(v.w);
        *(uint4*)&smH[r * HPAD + c4] = w;
    }
    int u  = tid & 31;
    int mb = warp * 8;
    float cst[8];
#pragma unroll
    for (int p = 0; p < 8; p++)
        cst[p] = c0p[((size_t)(dir * BB + bg * 64 + mb + p)) * HH + gg * 32 + u];
    __syncthreads();

    volatile int* vb = (volatile int*)(bars + grp);
    float hv[8];

    for (int t = 0; t < SQ; t++) {
        int te = dir ? (SQ - 1 - t) : t;

        // ---- (1) prefetch this step's xpre values into L2 during MMA ----
#pragma unroll
        for (int p = 0; p < 8; p++) {
            const float* xp = &xpre[(((size_t)(bg * 64 + mb + p)) * SQ + te) * G4 + gg * 32 + u];
            prefetchL2(xp);
            prefetchL2(xp + 256);
            prefetchL2(xp + 512);
            prefetchL2(xp + 768);
        }

        // ---- MMA phase (reads smH) ----
        float acc[8][4];
#pragma unroll
        for (int n = 0; n < 8; n++)
#pragma unroll
            for (int j = 0; j < 4; j++) acc[n][j] = 0.f;

        const unsigned* hA = smH + (mt * 16 + ly) * HPAD + lx;
#pragma unroll 4
        for (int k0 = 0; k0 < 256; k0 += 8) {
            unsigned a[4];
            a[0] = hA[k0];
            a[1] = hA[k0 + 8 * HPAD];
            a[2] = hA[k0 + 4];
            a[3] = hA[k0 + 8 * HPAD + 4];
#pragma unroll
            for (int nt = 0; nt < 8; nt++) {
                const unsigned* wB = smW + (nh * 64 + nt * 8 + ly) * WPAD + k0 + lx;
                mma_tf32(acc[nt], a, wB[0], wB[4]);
            }
        }
        __syncthreads();

#pragma unroll
        for (int nt = 0; nt < 8; nt++) {
            int n0 = nh * 64 + nt * 8 + lx * 2;
            int r0 = mt * 16 + ly;
            *(float2*)&smG[r0 * GPAD + n0]       = make_float2(acc[nt][0], acc[nt][1]);
            *(float2*)&smG[(r0 + 8) * GPAD + n0] = make_float2(acc[nt][2], acc[nt][3]);
        }
        __syncthreads();

#pragma unroll
        for (int p = 0; p < 8; p++) {
            int m = mb + p;
            const float* xp = &xpre[(((size_t)(bg * 64 + m)) * SQ + te) * G4 + gg * 32 + u];
            float gi = smG[m * GPAD +      u] + xp[0];
            float gf = smG[m * GPAD + 32 + u] + xp[256];
            float gc = smG[m * GPAD + 64 + u] + xp[512];
            float go = smG[m * GPAD + 96 + u] + xp[768];
            float i_ = 1.f / (1.f + __expf(-gi));
            float f_ = 1.f / (1.f + __expf(-gf));
            float g_ = tanhf(gc);
            float o_ = 1.f / (1.f + __expf(-go));
            float c  = f_ * cst[p] + i_ * g_;
            cst[p] = c;
            float h = rndtf(o_ * tanhf(c));
            hv[p] = h;
            Y[(((size_t)(seq * BB + bg * 64 + m)) * SQ + te) * D2 + dir * HH + gg * 32 + u] = h;
        }

        __threadfence();
        __syncthreads();
        if (tid == 0) {
            atomicAdd(bars + grp, 1);
            int target = 8 * (t + 1);
            while (*vb < target) { }
            __threadfence();
        }
        __syncthreads();

        // ---- (2) own chunk from registers; reload only the other 7 ----
#pragma unroll
        for (int p = 0; p < 8; p++)
            smH[(mb + p) * HPAD + gg * 32 + u] = f2tf(hv[p]);
        for (int i = tid; i < 64 * 64; i += 256) {
            if (((i & 63) >> 3) == gg) continue;      // own 32-col chunk
            int r = i >> 6, c4 = (i & 63) * 4;
            float4 v = __ldcg((const float4*)&Y[
                (((size_t)(seq * BB + bg * 64 + r)) * SQ + te) * D2 + dir * HH + c4]);
            uint4 w; w.x = f2tf(v.x); w.y = f2tf(v.y); w.z = f2tf(v.z); w.w = f2tf(v.w);
            *(uint4*)&smH[r * HPAD + c4] = w;
        }
        __syncthreads();
    }
}

// ---------------------------------------------------------------------------
// Softmax kernels (tf32-rounded outputs)
// ---------------------------------------------------------------------------
__global__ void row_softmax(const float* __restrict__ Hm, float* __restrict__ AQ)
{
    int warp = (blockIdx.x * blockDim.x + threadIdx.x) >> 5;
    int lane = threadIdx.x & 31;
    const float* base = Hm + (size_t)warp * SQ;
    float v[4], m = -1e30f;
#pragma unroll
    for (int u = 0; u < 4; u++) { v[u] = base[lane + 32 * u]; m = fmaxf(m, v[u]); }
#pragma unroll
    for (int o = 16; o > 0; o >>= 1) m = fmaxf(m, __shfl_xor_sync(0xffffffffu, m, o));
    float s = 0.f;
#pragma unroll
    for (int u = 0; u < 4; u++) { v[u] = __expf(v[u] - m); s += v[u]; }
#pragma unroll
    for (int o = 16; o > 0; o >>= 1) s += __shfl_xor_sync(0xffffffffu, s, o);
    float inv = 1.f / s;
    float* out = AQ + (size_t)warp * SQ;
#pragma unroll
    for (int u = 0; u < 4; u++) out[lane + 32 * u] = rndtf(v[u] * inv);
}

__global__ void col_softmax(const float* __restrict__ Hm, float* __restrict__ AC)
{
    int warp = (blockIdx.x * blockDim.x + threadIdx.x) >> 5;
    int lane = threadIdx.x & 31;
    int b = warp >> 7, s = warp & 127;
    const float* base = Hm + (size_t)b * SQ * SQ + s;
    float v[4], m = -1e30f;
#pragma unroll
    for (int u = 0; u < 4; u++) { v[u] = base[(size_t)(lane + 32 * u) * SQ]; m = fmaxf(m, v[u]); }
#pragma unroll
    for (int o = 16; o > 0; o >>= 1) m = fmaxf(m, __shfl_xor_sync(0xffffffffu, m, o));
    float sm = 0.f;
#pragma unroll
    for (int u = 0; u < 4; u++) { v[u] = __expf(v[u] - m); sm += v[u]; }
#pragma unroll
    for (int o = 16; o > 0; o >>= 1) sm += __shfl_xor_sync(0xffffffffu, sm, o);
    float inv = 1.f / sm;
    float* out = AC + (size_t)b * SQ * SQ + (size_t)s * SQ;
#pragma unroll
    for (int u = 0; u < 4; u++) out[lane + 32 * u] = rndtf(v[u] * inv);
}

// ---------------------------------------------------------------------------
// Host-side GEMM dispatch (dynamic smem)
// ---------------------------------------------------------------------------
static void run_tgemm(int epi, int M, int N, int K,
                      const float* A, int lda, size_t sA,
                      const float* B, int ldb, size_t sB,
                      float* C, int ldc, size_t sC,
                      const float* bias, int batch)
{
    dim3 grid(N / 128, M / 128, batch), block(256);
    size_t sh = TGEMM_SMEM_BYTES;
    if (epi == 0)      tgemm_kernel<0><<<grid, block, sh>>>(M, N, K, A, lda, sA, B, ldb, sB, C, ldc, sC, bias);
    else if (epi == 1) tgemm_kernel<1><<<grid, block, sh>>>(M, N, K, A, lda, sA, B, ldb, sB, C, ldc, sC, bias);
    else               tgemm_kernel<2><<<grid, block, sh>>>(M, N, K, A, lda, sA, B, ldb, sB, C, ldc, sC, bias);
}

// ---------------------------------------------------------------------------
// kernel_launch
// ---------------------------------------------------------------------------
extern "C" void kernel_launch(void* const* d_in, const int* in_sizes, int n_in,
                              void* d_out, int out_size)
{
    (void)in_sizes; (void)n_in; (void)out_size;
    const int*   inQ   = (const int*)d_in[1];
    const int*   inC   = (const int*)d_in[2];
    const int*   inC2  = (const int*)d_in[3];
    const float* hidQ  = (const float*)d_in[4];
    const float* celQ  = (const float*)d_in[5];
    const float* hidC  = (const float*)d_in[6];
    const float* celC  = (const float*)d_in[7];
    const float* hidC2 = (const float*)d_in[8];
    const float* celC2 = (const float*)d_in[9];
    const float* emb   = (const float*)d_in[10];
    const float* WihF  = (const float*)d_in[11];
    const float* WhhF  = (const float*)d_in[12];
    const float* bihF  = (const float*)d_in[13];
    const float* bhhF  = (const float*)d_in[14];
    const float* WihB  = (const float*)d_in[15];
    const float* WhhB  = (const float*)d_in[16];
    const float* bihB  = (const float*)d_in[17];
    const float* bhhB  = (const float*)d_in[18];
    const float* S1W   = (const float*)d_in[19];
    const float* S1b   = (const float*)d_in[20];
    float* out = (float*)d_out;

    void *pX, *pXpF, *pXpB, *pWFr, *pWBr, *pS1r, *pBf, *pBb, *pY, *pCt,
         *pYqT, *pMQT, *pHm, *pAQ, *pAC, *pBar;
    cudaGetSymbolAddress(&pX,   g_X);
    cudaGetSymbolAddress(&pXpF, g_XpreF);
    cudaGetSymbolAddress(&pXpB, g_XpreB);
    cudaGetSymbolAddress(&pWFr, g_WihFr);
    cudaGetSymbolAddress(&pWBr, g_WihBr);
    cudaGetSymbolAddress(&pS1r, g_S1Wr);
    cudaGetSymbolAddress(&pBf,  g_biasf);
    cudaGetSymbolAddress(&pBb,  g_biasb);
    cudaGetSymbolAddress(&pY,   g_Y);
    cudaGetSymbolAddress(&pCt,  g_Ct);
    cudaGetSymbolAddress(&pYqT, g_YqT);
    cudaGetSymbolAddress(&pMQT, g_MQT);
    cudaGetSymbolAddress(&pHm,  g_Hm);
    cudaGetSymbolAddress(&pAQ,  g_AQ);
    cudaGetSymbolAddress(&pAC,  g_AC);
    cudaGetSymbolAddress(&pBar, g_bar);
    float* X    = (float*)pX;
    float* XpF  = (float*)pXpF;
    float* XpB  = (float*)pXpB;
    float* WFr  = (float*)pWFr;
    float* WBr  = (float*)pWBr;
    float* S1r  = (float*)pS1r;
    float* Bf   = (float*)pBf;
    float* Bb   = (float*)pBb;
    float* Y    = (float*)pY;
    float* Ct   = (float*)pCt;
    float* YqT  = (float*)pYqT;
    float* MQT  = (float*)pMQT;
    float* Hm   = (float*)pHm;
    float* AQ   = (float*)pAQ;
    float* AC   = (float*)pAC;
    int*   bars = (int*)pBar;

    cudaFuncSetAttribute(lstm_mma_kernel,
                         cudaFuncAttributeMaxDynamicSharedMemorySize,
                         LSTM_SMEM_BYTES);
    cudaFuncSetAttribute(tgemm_kernel<0>,
                         cudaFuncAttributeMaxDynamicSharedMemorySize,
                         TGEMM_SMEM_BYTES);
    cudaFuncSetAttribute(tgemm_kernel<1>,
                         cudaFuncAttributeMaxDynamicSharedMemorySize,
                         TGEMM_SMEM_BYTES);
    cudaFuncSetAttribute(tgemm_kernel<2>,
                         cudaFuncAttributeMaxDynamicSharedMemorySize,
                         TGEMM_SMEM_BYTES);

    // 1. prep (launched twice — idempotent; shifts the ncu -s5 window onto lstm)
    prep_kernel<<<1024, 256>>>(bihF, bhhF, bihB, bhhB, WihF, WihB, S1W,
                               Bf, Bb, WFr, WBr, S1r, bars);
    prep_kernel<<<1024, 256>>>(bihF, bhhF, bihB, bhhB, WihF, WihB, S1W,
                               Bf, Bb, WFr, WBr, S1r, bars);

    // 2. embedding gather (rounded)
    embed_kernel<<<12288, 256>>>(inQ, inC, inC2, (const float4*)emb, (float4*)X);

    // 3. input GEMMs: Xpre = X @ Wih^T + (bih+bhh)
    run_tgemm(1, MX, G4, EE, X, EE, 0, WFr, EE, 0, XpF, G4, 0, Bf, 1);
    run_tgemm(1, MX, G4, EE, X, EE, 0, WBr, EE, 0, XpB, G4, 0, Bb, 1);

    // 4. recurrence (tensor-core, 96 resident CTAs, global-atomic exchange)
    lstm_mma_kernel<<<96, 256, LSTM_SMEM_BYTES>>>(
        XpF, XpB, WhhF, WhhB,
        hidQ, celQ, hidC, celC, hidC2, celC2, Y, bars);

    // 5. Ct = rndtf(tanh(Y_c @ S1_W^T + S1_b))
    run_tgemm(2, MBS, D2, D2, Y + (size_t)1 * MBS * D2, D2, 0,
              S1r, D2, 0, Ct, D2, 0, S1b, 1);
    run_tgemm(2, MBS, D2, D2, Y + (size_t)2 * MBS * D2, D2, 0,
              S1r, D2, 0, Ct + (size_t)MBS * D2, D2, 0, S1b, 1);

    // 5b. Yq^T for the MQ GEMM's B operand
    {
        dim3 tg(D2 / 32, SQ / 32, BB), tb(32, 8);
        transpose_kernel<<<tg, tb>>>(Y, YqT);
    }

    // 6. attention for pairs (Q,C) and (Q,C2)
    for (int p = 0; p < 2; p++) {
        run_tgemm(0, SQ, SQ, D2,
                  Y, D2, (size_t)SQ * D2,
                  Ct + (size_t)p * MBS * D2, D2, (size_t)SQ * D2,
                  Hm, SQ, (size_t)SQ * SQ, nullptr, BB);
        row_softmax<<<2048, 256>>>(Hm, AQ);
        col_softmax<<<2048, 256>>>(Hm, AC);
        float* outMQ = out + (size_t)(2 * p) * OUTREG;
        float* outMC = out + (size_t)(2 * p + 1) * OUTREG;
        run_tgemm(0, SQ, D2, SQ,
                  AQ, SQ, (size_t)SQ * SQ,
                  YqT, SQ, (size_t)SQ * D2,
                  outMQ, D2, (size_t)SQ * D2, nullptr, BB);
        {
            dim3 tg(D2 / 32, SQ / 32, BB), tb(32, 8);
            transpose_kernel<<<tg, tb>>>(outMQ, MQT);
        }
        run_tgemm(0, SQ, D2, SQ,
                  AC, SQ, (size_t)SQ * SQ,
                  MQT, SQ, (size_t)SQ * D2,
                  outMC, D2, (size_t)SQ * D2, nullptr, BB);
    }
}